// round 5
// baseline (speedup 1.0000x reference)
#include <cuda_runtime.h>
#include <cstdint>

// out[b, i*D+d, 0, t] = sum_c x[b,i,c,t] * renorm(w)[i*D+d, c]
#define B_ 32
#define I_ 16
#define C_ 128
#define T_ 2048
#define D_ 8
#define DEPTH 8   // cp.async pipeline depth (power of 2)

// Pre-renormed weights, duplicated as (w,w) u64 pairs for fma.f32x2. 16 KB.
__device__ unsigned long long g_ws2[I_ * D_ * C_];

__device__ __forceinline__ unsigned long long pack2(float lo, float hi) {
    unsigned long long r;
    asm("mov.b64 %0, {%1, %2};" : "=l"(r) : "f"(lo), "f"(hi));
    return r;
}
__device__ __forceinline__ void unpack2(unsigned long long v, float& lo, float& hi) {
    asm("mov.b64 {%0, %1}, %2;" : "=f"(lo), "=f"(hi) : "l"(v));
}
// Packed dual-fp32 FMA (Blackwell FFMA2, PTX-only).
__device__ __forceinline__ unsigned long long fma2(unsigned long long a,
                                                   unsigned long long b,
                                                   unsigned long long c) {
    unsigned long long d;
    asm("fma.rn.f32x2 %0, %1, %2, %3;" : "=l"(d) : "l"(a), "l"(b), "l"(c));
    return d;
}

__device__ __forceinline__ void cp_async16(uint32_t saddr, const float* gaddr) {
    asm volatile("cp.async.cg.shared.global [%0], [%1], 16;"
                 :: "r"(saddr), "l"(gaddr));
}
__device__ __forceinline__ void cp_commit() {
    asm volatile("cp.async.commit_group;" ::: "memory");
}
template <int N>
__device__ __forceinline__ void cp_wait() {
    asm volatile("cp.async.wait_group %0;" :: "n"(N) : "memory");
}

// ---------------------------------------------------------------------------
// Prep kernel: max-norm renorm, write duplicated (w,w) u64 weights. <<<16,256>>>
// ---------------------------------------------------------------------------
__global__ void prep_kernel(const float* __restrict__ w) {
    const int wid = threadIdx.x >> 5, lane = threadIdx.x & 31;
    const int row = blockIdx.x * 8 + wid;            // 0..127 = i*D+d
    const float* wr = w + row * C_;

    float v0 = wr[lane], v1 = wr[lane + 32], v2 = wr[lane + 64], v3 = wr[lane + 96];
    float s = v0 * v0 + v1 * v1 + v2 * v2 + v3 * v3;
    #pragma unroll
    for (int off = 16; off > 0; off >>= 1)
        s += __shfl_xor_sync(0xffffffffu, s, off);
    float n = sqrtf(s);
    float scale = (n > 1.0f) ? (1.0f / n) : 1.0f;

    unsigned long long* dst = g_ws2 + row * C_;
    dst[lane]      = pack2(v0 * scale, v0 * scale);
    dst[lane + 32] = pack2(v1 * scale, v1 * scale);
    dst[lane + 64] = pack2(v2 * scale, v2 * scale);
    dst[lane + 96] = pack2(v3 * scale, v3 * scale);
}

// ---------------------------------------------------------------------------
// Main kernel: grid = B*I = 512 (single resident wave). Block owns one (b,i)
// row: two 1024-t chunks back-to-back, cp.async pipeline continuous across
// the boundary. Two c's processed per inner iteration (LDS.128 weights).
// Linear load index n in [0,256): addr offset = ((n>>7)<<10) + (n&127)*T_.
// ---------------------------------------------------------------------------
__global__ __launch_bounds__(256, 4) void dwconv_kernel(
    const float* __restrict__ x,
    float* __restrict__ out)
{
    __shared__ __align__(16) float4 xs[DEPTH][256];            // 32 KB ring
    __shared__ __align__(16) unsigned long long ws2[D_ * C_];  // 8 KB weights

    const int tid = threadIdx.x;
    const int bid = blockIdx.x;          // 0..511 = b*I_ + i
    const int i = bid & (I_ - 1);
    const int b = bid >> 4;

    const int t0 = tid * 4;
    const float* xg = x + (size_t)bid * C_ * T_ + t0;   // (b,i) row base

    const uint32_t xs_base =
        (uint32_t)__cvta_generic_to_shared(&xs[0][0]) + (uint32_t)tid * 16u;

    // Warm up: first DEPTH loads (chunk 0, c = 0..7).
    #pragma unroll
    for (int s = 0; s < DEPTH; s++) {
        cp_async16(xs_base + (uint32_t)s * (256u * 16u), xg + (size_t)s * T_);
        cp_commit();
    }

    // Copy this i's renormed weights (8 KB) into smem — once for both chunks.
    {
        const float4* gw4 = reinterpret_cast<const float4*>(g_ws2 + i * (D_ * C_));
        float4* sw4 = reinterpret_cast<float4*>(ws2);
        sw4[tid]       = gw4[tid];
        sw4[tid + 256] = gw4[tid + 256];
    }
    __syncthreads();

    #pragma unroll 1
    for (int chunk = 0; chunk < 2; chunk++) {
        unsigned long long acc01[D_], acc23[D_];
        #pragma unroll
        for (int d = 0; d < D_; d++) { acc01[d] = 0ull; acc23[d] = 0ull; }

        #pragma unroll 4
        for (int c = 0; c < C_; c += 2) {
            const int n = chunk * C_ + c;     // linear consume index

            cp_wait<DEPTH - 2>();             // loads n and n+1 have landed

            float4 xa = xs[n & (DEPTH - 1)][tid];
            float4 xb = xs[(n + 1) & (DEPTH - 1)][tid];
            unsigned long long xa01 = pack2(xa.x, xa.y);
            unsigned long long xa23 = pack2(xa.z, xa.w);
            unsigned long long xb01 = pack2(xb.x, xb.y);
            unsigned long long xb23 = pack2(xb.z, xb.w);

            #pragma unroll
            for (int d = 0; d < D_; d++) {
                ulonglong2 wv =
                    *reinterpret_cast<const ulonglong2*>(&ws2[d * C_ + c]);
                acc01[d] = fma2(xa01, wv.x, acc01[d]);
                acc23[d] = fma2(xa23, wv.x, acc23[d]);
                acc01[d] = fma2(xb01, wv.y, acc01[d]);
                acc23[d] = fma2(xb23, wv.y, acc23[d]);
            }

            // Refill the two consumed slots with loads n+8, n+9 (if in range).
            #pragma unroll
            for (int k = 0; k < 2; k++) {
                const int m = n + DEPTH + k;
                if (m < 2 * C_) {
                    const size_t off = (size_t)((m >> 7) << 10)   // chunk*1024
                                     + (size_t)(m & (C_ - 1)) * T_;
                    cp_async16(xs_base + (uint32_t)(m & (DEPTH - 1)) * (256u * 16u),
                               xg + off);
                }
                cp_commit();   // commit every slot (possibly empty) for accounting
            }
        }

        float4* __restrict__ op = reinterpret_cast<float4*>(
            out + (size_t)bid * (D_ * T_) + chunk * 1024 + t0);
        #pragma unroll
        for (int d = 0; d < D_; d++) {
            float4 o;
            unpack2(acc01[d], o.x, o.y);
            unpack2(acc23[d], o.z, o.w);
            op[(size_t)d * (T_ / 4)] = o;
        }
    }
}

extern "C" void kernel_launch(void* const* d_in, const int* in_sizes, int n_in,
                              void* d_out, int out_size) {
    const float* x = (const float*)d_in[0];   // (32,16,128,2048) fp32
    const float* w = (const float*)d_in[1];   // (256,1,128,1)    fp32
    float* out = (float*)d_out;               // (32,256,1,2048)  fp32
    (void)in_sizes; (void)n_in; (void)out_size;

    prep_kernel<<<16, 256>>>(w);
    dwconv_kernel<<<B_ * I_, 256>>>(x, out);
}

// round 6
// speedup vs baseline: 1.0870x; 1.0870x over previous
#include <cuda_runtime.h>
#include <cstdint>

// out[b, i*D+d, 0, t] = sum_c x[b,i,c,t] * renorm(w)[i*D+d, c]
#define B_ 32
#define I_ 16
#define C_ 128
#define T_ 2048
#define D_ 8
#define DEPTH 8   // cp.async pipeline depth (power of 2)

__device__ __forceinline__ unsigned long long pack2(float lo, float hi) {
    unsigned long long r;
    asm("mov.b64 %0, {%1, %2};" : "=l"(r) : "f"(lo), "f"(hi));
    return r;
}
__device__ __forceinline__ void unpack2(unsigned long long v, float& lo, float& hi) {
    asm("mov.b64 {%0, %1}, %2;" : "=f"(lo), "=f"(hi) : "l"(v));
}
// Packed dual-fp32 FMA (Blackwell FFMA2, PTX-only).
__device__ __forceinline__ unsigned long long fma2(unsigned long long a,
                                                   unsigned long long b,
                                                   unsigned long long c) {
    unsigned long long d;
    asm("fma.rn.f32x2 %0, %1, %2, %3;" : "=l"(d) : "l"(a), "l"(b), "l"(c));
    return d;
}

__device__ __forceinline__ void cp_async16(uint32_t saddr, const float* gaddr) {
    asm volatile("cp.async.cg.shared.global [%0], [%1], 16;"
                 :: "r"(saddr), "l"(gaddr));
}
__device__ __forceinline__ void cp_commit() {
    asm volatile("cp.async.commit_group;" ::: "memory");
}
template <int N>
__device__ __forceinline__ void cp_wait() {
    asm volatile("cp.async.wait_group %0;" :: "n"(N) : "memory");
}

// ---------------------------------------------------------------------------
// Single fused kernel. Block = one (b, i, t-chunk of 1024); thread owns 4
// consecutive t. x streamed through an 8-deep thread-private cp.async ring.
// Weights: renormed in-block during the warmup shadow, stored TRANSPOSED and
// duplicated in smem as ws2t[c][d] (u64 (w,w) pairs) so each c needs only
// 4 broadcast LDS.128 (cuts weight smem wavefronts 4x vs [d][c] LDS.64).
// ---------------------------------------------------------------------------
__global__ __launch_bounds__(256, 4) void dwconv_kernel(
    const float* __restrict__ x,
    const float* __restrict__ w,
    float* __restrict__ out)
{
    __shared__ __align__(16) float4 xs[DEPTH][256];              // 32 KB ring
    __shared__ __align__(16) unsigned long long ws2t[C_ * D_];   // 8 KB, [c][d]

    const int tid = threadIdx.x;
    const int bid = blockIdx.x;
    const int tchunk = bid & 1;
    const int i      = (bid >> 1) & (I_ - 1);
    const int b      = bid >> 5;

    const int t0 = tchunk * 1024 + tid * 4;
    const float* xg = x + (size_t)(b * I_ + i) * C_ * T_ + t0;

    const uint32_t xs_base =
        (uint32_t)__cvta_generic_to_shared(&xs[0][0]) + (uint32_t)tid * 16u;

    // Kick off the pipeline before anything else touches memory.
    #pragma unroll
    for (int s = 0; s < DEPTH; s++) {
        cp_async16(xs_base + (uint32_t)s * (256u * 16u), xg + (size_t)s * T_);
        cp_commit();
    }

    // Renorm this i's weights in-block (hidden under warmup load latency).
    // Warp wid owns row d = wid: load 128 floats, reduce L2 norm, write
    // transposed duplicated pairs ws2t[c*D + wid] = (w*s, w*s).
    {
        const int wid = tid >> 5, lane = tid & 31;
        const float* wr = w + (i * D_ + wid) * C_;
        float v0 = wr[lane], v1 = wr[lane + 32],
              v2 = wr[lane + 64], v3 = wr[lane + 96];
        float s = v0 * v0 + v1 * v1 + v2 * v2 + v3 * v3;
        #pragma unroll
        for (int off = 16; off > 0; off >>= 1)
            s += __shfl_xor_sync(0xffffffffu, s, off);
        float n = sqrtf(s);
        float sc = (n > 1.0f) ? (1.0f / n) : 1.0f;
        v0 *= sc; v1 *= sc; v2 *= sc; v3 *= sc;
        ws2t[(lane      ) * D_ + wid] = pack2(v0, v0);
        ws2t[(lane + 32 ) * D_ + wid] = pack2(v1, v1);
        ws2t[(lane + 64 ) * D_ + wid] = pack2(v2, v2);
        ws2t[(lane + 96 ) * D_ + wid] = pack2(v3, v3);
    }
    __syncthreads();

    unsigned long long acc01[D_], acc23[D_];
    #pragma unroll
    for (int d = 0; d < D_; d++) { acc01[d] = 0ull; acc23[d] = 0ull; }

    const float* xg_pf = xg + (size_t)DEPTH * T_;   // prefetch pointer base

    #pragma unroll 8
    for (int c = 0; c < C_; c++) {
        cp_wait<DEPTH - 1>();   // oldest group (stage c) landed

        float4 xv = xs[c & (DEPTH - 1)][tid];
        unsigned long long x01 = pack2(xv.x, xv.y);
        unsigned long long x23 = pack2(xv.z, xv.w);

        const ulonglong2* __restrict__ wt =
            reinterpret_cast<const ulonglong2*>(ws2t + c * D_);
        #pragma unroll
        for (int dd = 0; dd < D_ / 2; dd++) {
            ulonglong2 wv = wt[dd];          // broadcast LDS.128: d=2dd, 2dd+1
            acc01[2 * dd]     = fma2(x01, wv.x, acc01[2 * dd]);
            acc23[2 * dd]     = fma2(x23, wv.x, acc23[2 * dd]);
            acc01[2 * dd + 1] = fma2(x01, wv.y, acc01[2 * dd + 1]);
            acc23[2 * dd + 1] = fma2(x23, wv.y, acc23[2 * dd + 1]);
        }

        // Refill the slot just consumed (thread-private: no barrier needed).
        if (c < C_ - DEPTH)
            cp_async16(xs_base + (uint32_t)(c & (DEPTH - 1)) * (256u * 16u),
                       xg_pf + (size_t)c * T_);
        cp_commit();   // commit every iter (possibly empty) to keep accounting
    }

    float4* __restrict__ op = reinterpret_cast<float4*>(
        out + (size_t)(b * (I_ * D_) + i * D_) * T_ + t0);
    #pragma unroll
    for (int d = 0; d < D_; d++) {
        float4 o;
        unpack2(acc01[d], o.x, o.y);
        unpack2(acc23[d], o.z, o.w);
        op[(size_t)d * (T_ / 4)] = o;
    }
}

extern "C" void kernel_launch(void* const* d_in, const int* in_sizes, int n_in,
                              void* d_out, int out_size) {
    const float* x = (const float*)d_in[0];   // (32,16,128,2048) fp32
    const float* w = (const float*)d_in[1];   // (256,1,128,1)    fp32
    float* out = (float*)d_out;               // (32,256,1,2048)  fp32
    (void)in_sizes; (void)n_in; (void)out_size;

    dwconv_kernel<<<B_ * I_ * (T_ / 1024), 256>>>(x, w, out);
}